// round 17
// baseline (speedup 1.0000x reference)
#include <cuda_runtime.h>
#include <math.h>
#include <stdint.h>

#define BB    256
#define NN    32
#define FF    40
#define HH    100
#define MM    100
#define EFN   4
#define OUTD  128
#define H3    300
#define KMAX  8
#define NODES (BB*NN)   // 8192
#define TPAD  40        // T row stride (floats)
#define NTHR  416

typedef unsigned long long ull;
typedef unsigned int u32;

// ---------------- device scratch ----------------
__device__ __align__(16) ull  g_WmD[EFN*HH*MM];      // [f][k][m] dup'd {w,w}
__device__ __align__(16) ull  g_WpD[HH*HH*6];        // [k][h][6] dup'd: ihR,ihZ,ihN,hhR,hhZ,hhN
__device__ __align__(16) ulonglong2 g_WgeD[140*HH];  // [k][h] = {dup(wg), dup(we)}
__device__ int   g_nbr[NODES*KMAX];
__device__ int   g_typ[NODES*KMAX];
__device__ float g_wgt[NODES*KMAX];
__device__ int   g_cnt[NODES];

__device__ __forceinline__ float sigmf(float x) { return 1.0f / (1.0f + expf(-x)); }
__device__ __forceinline__ ull packdup(float w) {
    ull r; asm("mov.b64 %0,{%1,%1};" : "=l"(r) : "f"(w)); return r;
}
__device__ __forceinline__ void unpack2(ull v, float& lo, float& hi) {
    asm("mov.b64 {%0,%1},%2;" : "=f"(lo), "=f"(hi) : "l"(v));
}
__device__ __forceinline__ void fma2(ull& d, ull a, ull b) {
    asm("fma.rn.f32x2 %0, %1, %2, %0;" : "+l"(d) : "l"(a), "l"(b));
}

// ---------------- combined prep: edges + all weight relayouts, ONE launch ----
__global__ void prep_all(const float* __restrict__ edges,
                         const float* __restrict__ W_msg,
                         const float* __restrict__ W_ih,
                         const float* __restrict__ W_hh,
                         const float* __restrict__ Wg,
                         const float* __restrict__ We) {
    const int gid  = blockIdx.x * blockDim.x + threadIdx.x;
    const int warp = gid >> 5;
    const int lane = threadIdx.x & 31;

    // ---- edge compaction (warp per node) ----
    if (warp < NODES) {
        int p = warp;
        float4 v = ((const float4*)edges)[(size_t)p * NN + lane];
        float vv[4] = {v.x, v.y, v.z, v.w};
        int nl = (vv[0]!=0.f) + (vv[1]!=0.f) + (vv[2]!=0.f) + (vv[3]!=0.f);
        int inc = nl;
        #pragma unroll
        for (int off = 1; off < 32; off <<= 1) {
            int t = __shfl_up_sync(0xFFFFFFFFu, inc, off);
            if (lane >= off) inc += t;
        }
        int excl = inc - nl;
        int total = __shfl_sync(0xFFFFFFFFu, inc, 31);
        int c = excl;
        #pragma unroll
        for (int f = 0; f < EFN; f++) {
            if (vv[f] != 0.f && c < KMAX) {
                g_nbr[p*KMAX + c] = lane;
                g_typ[p*KMAX + c] = f;
                g_wgt[p*KMAX + c] = vv[f];
                c++;
            }
        }
        if (lane == 0) g_cnt[p] = (total < KMAX) ? total : KMAX;
    }

    // ---- weight relayouts (disjoint gid ranges) ----
    const int NWT = EFN*HH*MM;            // 40000
    if (gid < NWT) {
        int f = gid / (HH*MM);
        int rem = gid % (HH*MM);
        int k = rem / MM;
        int m = rem % MM;
        g_WmD[gid] = packdup(W_msg[(m*HH + k)*EFN + f]);
    } else if (gid < NWT + HH*HH) {       // 10000 (k,h) entries
        int t = gid - NWT;
        int k = t / HH, h = t % HH;
        ull* dst = g_WpD + (size_t)t*6;
        dst[0] = packdup(W_ih[(h)*HH + k]);
        dst[1] = packdup(W_ih[(100+h)*HH + k]);
        dst[2] = packdup(W_ih[(200+h)*HH + k]);
        dst[3] = packdup(W_hh[(h)*HH + k]);
        dst[4] = packdup(W_hh[(100+h)*HH + k]);
        dst[5] = packdup(W_hh[(200+h)*HH + k]);
    } else if (gid < NWT + HH*HH + 140*HH) {
        int t = gid - NWT - HH*HH;
        int k = t / HH, h = t % HH;
        float wg = Wg[k*HH + h];
        float we = (k < HH) ? We[k*HH + h] : 0.0f;
        g_WgeD[t] = make_ulonglong2(packdup(wg), packdup(we));
    }
}

// ---------------- fused: 3 passes + readout, one block per batch ----------
__global__ __launch_bounds__(NTHR, 2) void fused_kernel(
        const float* __restrict__ nodes,
        const float* __restrict__ b_ih, const float* __restrict__ b_hh,
        const float* __restrict__ bg,   const float* __restrict__ be,
        const float* __restrict__ Wo,   const float* __restrict__ bo,
        float* __restrict__ out) {
    __shared__ __align__(16) float sh_h[HH*NN];          // [k][n] 12.8KB
    __shared__ __align__(16) float sh_T[EFN*HH*TPAD];    // 64KB: T tiles
    __shared__ __align__(16) float sh_msg[HH*NN];        // [k][n] 12.8KB
    __shared__ __align__(16) float sh_x[FF*NN];          // 5.1KB
    __shared__ int   sh_nbr[NN][KMAX];
    __shared__ int   sh_typ[NN][KMAX];
    __shared__ float sh_wgt[NN][KMAX];
    __shared__ int   sh_cnt[NN];
    __shared__ float sh_part[4*HH];
    __shared__ float sh_acc[HH];

    const int b   = blockIdx.x;
    const int tid = threadIdx.x;
    const int p0  = b * NN;

    // edge meta
    if (tid < NN) sh_cnt[tid] = g_cnt[p0 + tid];
    else if (tid >= 32 && tid < 32 + NN*KMAX) {
        int t = tid - 32; int n = t >> 3, e = t & 7;
        sh_nbr[n][e] = g_nbr[(p0+n)*KMAX + e];
        sh_typ[n][e] = g_typ[(p0+n)*KMAX + e];
        sh_wgt[n][e] = g_wgt[(p0+n)*KMAX + e];
    }
    // hidden init: [nodes | 0]
    for (int idx = tid; idx < HH*NN; idx += NTHR) {
        int k = idx >> 5, n = idx & 31;
        sh_h[idx] = (k < FF) ? nodes[(size_t)(p0+n)*FF + k] : 0.0f;
    }
    __syncthreads();

    const int hh = (tid < 400) ? (tid % 100) : 0;
    const int ng = (tid < 400) ? (tid / 100) : 0;

    // hoisted GRU biases (constant across passes)
    float brz = 0.f, bzz = 0.f, bin = 0.f, bhn = 0.f;
    if (tid < 400) {
        brz = b_ih[hh]       + b_hh[hh];
        bzz = b_ih[100 + hh] + b_hh[100 + hh];
        bin = b_ih[200 + hh];
        bhn = b_hh[200 + hh];
    }

    for (int pass = 0; pass < 3; pass++) {
        // ---- T[f][m][n] = sum_k Wm[f][k][m] * h[k][n] -- 4m x 8n register tile ----
        if (tid < 400) {
            const int f  = tid / 100, r = tid - f*100;
            const int mq = r >> 2;          // m base = mq*4
            const int nt = r & 3;           // node octet: nt*8
            ull acc[4][4];
            #pragma unroll
            for (int i = 0; i < 4; i++)
                #pragma unroll
                for (int j = 0; j < 4; j++) acc[i][j] = 0ull;
            const ulonglong2* Wd = (const ulonglong2*)(g_WmD + (size_t)(f*HH)*MM);
            for (int k = 0; k < HH; k++) {
                ulonglong2 wA = Wd[k*50 + mq*2];
                ulonglong2 wB = Wd[k*50 + mq*2 + 1];
                const ulonglong2* hp = (const ulonglong2*)(sh_h + k*NN + nt*8);
                ulonglong2 d0 = hp[0], d1 = hp[1];
                fma2(acc[0][0], wA.x, d0.x); fma2(acc[0][1], wA.x, d0.y);
                fma2(acc[0][2], wA.x, d1.x); fma2(acc[0][3], wA.x, d1.y);
                fma2(acc[1][0], wA.y, d0.x); fma2(acc[1][1], wA.y, d0.y);
                fma2(acc[1][2], wA.y, d1.x); fma2(acc[1][3], wA.y, d1.y);
                fma2(acc[2][0], wB.x, d0.x); fma2(acc[2][1], wB.x, d0.y);
                fma2(acc[2][2], wB.x, d1.x); fma2(acc[2][3], wB.x, d1.y);
                fma2(acc[3][0], wB.y, d0.x); fma2(acc[3][1], wB.y, d0.y);
                fma2(acc[3][2], wB.y, d1.x); fma2(acc[3][3], wB.y, d1.y);
            }
            #pragma unroll
            for (int mi = 0; mi < 4; mi++) {
                ulonglong2* dst = (ulonglong2*)(sh_T + (size_t)(f*MM + mq*4 + mi)*TPAD + nt*8);
                dst[0] = make_ulonglong2(acc[mi][0], acc[mi][1]);
                dst[1] = make_ulonglong2(acc[mi][2], acc[mi][3]);
            }
        }
        __syncthreads();

        // ---- gather: msg[m][n] = sum_e w_e * T[f_e][m][g_e] -> sh_msg ----
        if (tid < 400) {
            const int m = tid >> 2;
            const int n0 = (tid & 3) * 8;
            float res[8];
            #pragma unroll
            for (int j = 0; j < 8; j++) {
                int n = n0 + j;
                int c = sh_cnt[n];
                float s = 0.f;
                for (int e = 0; e < c; e++) {
                    s += sh_wgt[n][e] *
                         sh_T[(size_t)(sh_typ[n][e]*MM + m)*TPAD + sh_nbr[n][e]];
                }
                res[j] = s;
            }
            float4* dst = (float4*)(sh_msg + (size_t)m*NN + n0);
            dst[0] = make_float4(res[0], res[1], res[2], res[3]);
            dst[1] = make_float4(res[4], res[5], res[6], res[7]);
        }
        __syncthreads();   // msg visible

        // ---- GRU: direct dup'd LDG weights, mov-free inner loop ----
        ull accA[4], accB[4], accC[4], accD[4];
        #pragma unroll
        for (int j = 0; j < 4; j++) { accA[j]=0; accB[j]=0; accC[j]=0; accD[j]=0; }

        if (tid < 400) {
            const ulonglong2* W0 = (const ulonglong2*)(g_WpD + hh*6);
            for (int k = 0; k < HH; k++) {
                const ulonglong2* wp = W0 + k*300;   // k*600 ull = k*300 ulonglong2
                ulonglong2 wA = wp[0];   // {ihR, ihZ}
                ulonglong2 wB = wp[1];   // {ihN, hhR}
                ulonglong2 wC = wp[2];   // {hhZ, hhN}
                const ulonglong2* mp = (const ulonglong2*)(sh_msg + (size_t)k*NN + ng*8);
                const ulonglong2* hp = (const ulonglong2*)(sh_h + k*NN + ng*8);
                ulonglong2 m01 = mp[0], m23 = mp[1];
                ulonglong2 h01 = hp[0], h23 = hp[1];
                fma2(accA[0], wA.x, m01.x); fma2(accA[0], wB.y, h01.x);
                fma2(accA[1], wA.x, m01.y); fma2(accA[1], wB.y, h01.y);
                fma2(accA[2], wA.x, m23.x); fma2(accA[2], wB.y, h23.x);
                fma2(accA[3], wA.x, m23.y); fma2(accA[3], wB.y, h23.y);
                fma2(accB[0], wA.y, m01.x); fma2(accB[0], wC.x, h01.x);
                fma2(accB[1], wA.y, m01.y); fma2(accB[1], wC.x, h01.y);
                fma2(accB[2], wA.y, m23.x); fma2(accB[2], wC.x, h23.x);
                fma2(accB[3], wA.y, m23.y); fma2(accB[3], wC.x, h23.y);
                fma2(accC[0], wB.x, m01.x); fma2(accC[1], wB.x, m01.y);
                fma2(accC[2], wB.x, m23.x); fma2(accC[3], wB.x, m23.y);
                fma2(accD[0], wC.y, h01.x); fma2(accD[1], wC.y, h01.y);
                fma2(accD[2], wC.y, h23.x); fma2(accD[3], wC.y, h23.y);
            }
        }

        // previous h values for this (h, 8 nodes)
        ull hv[4];
        if (tid < 400) {
            const ulonglong2* hvp = (const ulonglong2*)(sh_h + hh*NN + ng*8);
            ulonglong2 a = hvp[0], c = hvp[1];
            hv[0] = a.x; hv[1] = a.y; hv[2] = c.x; hv[3] = c.y;
        }
        __syncthreads();   // all reads of sh_h / sh_msg done

        if (tid < 400) {
            float o[8];
            #pragma unroll
            for (int j = 0; j < 4; j++) {
                float a0, a1, zb0, zb1, c0, c1, d0, d1, h0, h1;
                unpack2(accA[j], a0, a1);
                unpack2(accB[j], zb0, zb1);
                unpack2(accC[j], c0, c1);
                unpack2(accD[j], d0, d1);
                unpack2(hv[j], h0, h1);
                int nA = ng*8 + 2*j, nB = nA + 1;
                {
                    float r = sigmf(a0 + brz);
                    float z = sigmf(zb0 + bzz);
                    float nv = tanhf(c0 + bin + r*(d0 + bhn));
                    o[2*j]   = (sh_cnt[nA] == 0) ? h0 : (1.0f - z)*nv + z*h0;
                }
                {
                    float r = sigmf(a1 + brz);
                    float z = sigmf(zb1 + bzz);
                    float nv = tanhf(c1 + bin + r*(d1 + bhn));
                    o[2*j+1] = (sh_cnt[nB] == 0) ? h1 : (1.0f - z)*nv + z*h1;
                }
            }
            float4* dst = (float4*)(sh_h + hh*NN + ng*8);
            dst[0] = make_float4(o[0], o[1], o[2], o[3]);
            dst[1] = make_float4(o[4], o[5], o[6], o[7]);
        }
        __syncthreads();
    }

    // ---- readout ----
    for (int idx = tid; idx < NN*FF; idx += NTHR) {
        int n = idx / FF, k = idx % FF;
        sh_x[k*NN + n] = nodes[(size_t)(p0+n)*FF + k];
    }
    __syncthreads();

    if (tid < 400) {
        ull ga[4], ev[4];
        #pragma unroll
        for (int j = 0; j < 4; j++) { ga[j] = 0; ev[j] = 0; }
        const ulonglong2* WD = g_WgeD + hh;
        for (int k = 0; k < HH; k++) {
            ulonglong2 w = WD[k*HH];
            const ulonglong2* hp = (const ulonglong2*)(sh_h + k*NN + ng*8);
            ulonglong2 a = hp[0], c = hp[1];
            fma2(ga[0], w.x, a.x); fma2(ga[1], w.x, a.y);
            fma2(ga[2], w.x, c.x); fma2(ga[3], w.x, c.y);
            fma2(ev[0], w.y, a.x); fma2(ev[1], w.y, a.y);
            fma2(ev[2], w.y, c.x); fma2(ev[3], w.y, c.y);
        }
        for (int k = 0; k < FF; k++) {
            ulonglong2 w = WD[(HH + k)*HH];
            const ulonglong2* xp = (const ulonglong2*)(sh_x + k*NN + ng*8);
            ulonglong2 a = xp[0], c = xp[1];
            fma2(ga[0], w.x, a.x); fma2(ga[1], w.x, a.y);
            fma2(ga[2], w.x, c.x); fma2(ga[3], w.x, c.y);
        }
        float bgv = bg[hh], bev = be[hh];
        float s = 0.f;
        #pragma unroll
        for (int j = 0; j < 4; j++) {
            float gl, gh_, el, eh;
            unpack2(ga[j], gl, gh_);
            unpack2(ev[j], el, eh);
            int nA = ng*8 + 2*j, nB = nA + 1;
            if (sh_cnt[nA] != 0) s += sigmf(gl + bgv) * (el + bev);
            if (sh_cnt[nB] != 0) s += sigmf(gh_ + bgv) * (eh + bev);
        }
        sh_part[ng*HH + hh] = s;
    }
    __syncthreads();
    if (tid < HH)
        sh_acc[tid] = sh_part[tid] + sh_part[HH + tid] + sh_part[2*HH + tid] + sh_part[3*HH + tid];
    __syncthreads();

    if (tid < OUTD) {
        float v = bo[tid];
        #pragma unroll 4
        for (int k = 0; k < HH; k++) v += sh_acc[k] * Wo[k*OUTD + tid];
        out[(size_t)b*OUTD + tid] = v;
    }
}

// ---------------- launcher ----------------
extern "C" void kernel_launch(void* const* d_in, const int* in_sizes, int n_in,
                              void* d_out, int out_size) {
    const float* nodes = (const float*)d_in[0];
    const float* edges = (const float*)d_in[1];
    const float* W_msg = (const float*)d_in[2];
    const float* W_ih  = (const float*)d_in[3];
    const float* W_hh  = (const float*)d_in[4];
    const float* b_ih  = (const float*)d_in[5];
    const float* b_hh  = (const float*)d_in[6];
    const float* Wg    = (const float*)d_in[7];
    const float* bg    = (const float*)d_in[8];
    const float* We    = (const float*)d_in[9];
    const float* be    = (const float*)d_in[10];
    const float* Wo    = (const float*)d_in[11];
    const float* bo    = (const float*)d_in[12];
    float* out = (float*)d_out;

    prep_all<<<1024, 256>>>(edges, W_msg, W_ih, W_hh, Wg, We);
    fused_kernel<<<BB, NTHR>>>(nodes, b_ih, b_hh, bg, be, Wo, bo, out);
}